// round 2
// baseline (speedup 1.0000x reference)
#include <cuda_runtime.h>

#define BLOCK 256
#define OPT 2
#define OUTB (BLOCK * OPT)
#define HALO_L 10
#define HALO_R 3
#define TILE (OUTB + HALO_L + HALO_R + 1)   // 526 samples

// Merged, packed coefficient table: Q[l][e3][k] as (re,im) packed in b64.
// e3 = e+3, e in [-3,3]:
//   e=0  : a[k,l] + b[k,l,0] + c[k,l,0]
//   e=-m : b[k,l,m]   (m=1..3)
//   e=+m : c[k,l,m]   (m=1..3)
__device__ unsigned long long g_Q[448];

static __device__ __forceinline__ unsigned long long pk2(float a, float b) {
    unsigned long long v;
    asm("mov.b64 %0,{%1,%2};" : "=l"(v) : "f"(a), "f"(b));
    return v;
}
static __device__ __forceinline__ void up2(unsigned long long v, float& a, float& b) {
    asm("mov.b64 {%0,%1},%2;" : "=f"(a), "=f"(b) : "l"(v));
}
static __device__ __forceinline__ unsigned long long fma2(unsigned long long a,
                                                          unsigned long long b,
                                                          unsigned long long c) {
    unsigned long long d;
    asm("fma.rn.f32x2 %0,%1,%2,%3;" : "=l"(d) : "l"(a), "l"(b), "l"(c));
    return d;
}
static __device__ __forceinline__ unsigned long long add2(unsigned long long a,
                                                           unsigned long long b) {
    unsigned long long d;
    asm("add.rn.f32x2 %0,%1,%2;" : "=l"(d) : "l"(a), "l"(b));
    return d;
}

__global__ void gmp_prep_kernel(const float* __restrict__ ar, const float* __restrict__ ai,
                                const float* __restrict__ br, const float* __restrict__ bi,
                                const float* __restrict__ cr, const float* __restrict__ ci) {
    int i = threadIdx.x;
    if (i >= 448) return;
    int k  = i & 7;
    int e3 = (i >> 3) % 7;
    int l  = i / 56;
    int kl = k * 8 + l;          // a[k,l] row-major (Ka=8, La=8)
    float re, im;
    if (e3 == 3) {
        re = ar[kl] + br[kl * 4 + 0] + cr[kl * 4 + 0];
        im = ai[kl] + bi[kl * 4 + 0] + ci[kl * 4 + 0];
    } else if (e3 < 3) {
        int m = 3 - e3;
        re = br[kl * 4 + m];
        im = bi[kl * 4 + m];
    } else {
        int m = e3 - 3;
        re = cr[kl * 4 + m];
        im = ci[kl * 4 + m];
    }
    g_Q[(l * 7 + e3) * 8 + k] = pk2(re, im);
}

__global__ __launch_bounds__(BLOCK)
void gmp_main_kernel(const float2* __restrict__ x, float2* __restrict__ y, int N) {
    __shared__ float2 sx[TILE];
    __shared__ unsigned long long srr[TILE];   // (r, r) packed per sample
    __shared__ unsigned long long sQ[448];

    int t = threadIdx.x;
    int base = blockIdx.x * OUTB;

    for (int i = t; i < TILE; i += BLOCK) {
        int g = base - HALO_L + i;
        g = min(max(g, 0), N - 1);             // index clipping == clamp at load
        float2 v = x[g];
        sx[i] = v;
        float r = sqrtf(v.x * v.x + v.y * v.y);
        srr[i] = pk2(r, r);
    }
    for (int i = t; i < 448; i += BLOCK) sQ[i] = g_Q[i];
    __syncthreads();

    float yr0 = 0.f, yi0 = 0.f, yr1 = 0.f, yi1 = 0.f;
    const int s0 = t + HALO_L;
    const int s1 = t + BLOCK + HALO_L;

    #pragma unroll 1
    for (int l = 0; l < 8; l++) {
        unsigned long long w0 = 0ULL, w1 = 0ULL;   // packed (0,0)
        const unsigned long long* Q = &sQ[l * 7 * 8];
        #pragma unroll
        for (int e3 = 0; e3 < 7; e3++) {
            int off = e3 - 3 - l;
            unsigned long long r0 = srr[s0 + off];
            unsigned long long r1 = srr[s1 + off];
            unsigned long long h0 = Q[e3 * 8 + 7];
            unsigned long long h1 = h0;
            #pragma unroll
            for (int k = 6; k >= 0; k--) {
                unsigned long long c = Q[e3 * 8 + k];
                h0 = fma2(h0, r0, c);
                h1 = fma2(h1, r1, c);
            }
            w0 = add2(w0, h0);
            w1 = add2(w1, h1);
        }
        float2 xl0 = sx[s0 - l];
        float2 xl1 = sx[s1 - l];
        float wr0, wi0, wr1, wi1;
        up2(w0, wr0, wi0);
        up2(w1, wr1, wi1);
        // y += x * w  (complex)
        yr0 = fmaf(xl0.x, wr0, fmaf(-xl0.y, wi0, yr0));
        yi0 = fmaf(xl0.x, wi0, fmaf( xl0.y, wr0, yi0));
        yr1 = fmaf(xl1.x, wr1, fmaf(-xl1.y, wi1, yr1));
        yi1 = fmaf(xl1.x, wi1, fmaf( xl1.y, wr1, yi1));
    }

    int n0 = base + t;
    if (n0 < N)         y[n0]         = make_float2(yr0, yi0);
    if (n0 + BLOCK < N) y[n0 + BLOCK] = make_float2(yr1, yi1);
}

extern "C" void kernel_launch(void* const* d_in, const int* in_sizes, int n_in,
                              void* d_out, int out_size) {
    const float2* x  = (const float2*)d_in[0];
    const float*  ar = (const float*)d_in[1];
    const float*  ai = (const float*)d_in[2];
    const float*  br = (const float*)d_in[3];
    const float*  bi = (const float*)d_in[4];
    const float*  cr = (const float*)d_in[5];
    const float*  ci = (const float*)d_in[6];
    float2* y = (float2*)d_out;
    int N = in_sizes[0] / 2;

    gmp_prep_kernel<<<1, 448>>>(ar, ai, br, bi, cr, ci);
    int grid = (N + OUTB - 1) / OUTB;
    gmp_main_kernel<<<grid, BLOCK>>>(x, y, N);
}

// round 3
// speedup vs baseline: 1.1233x; 1.1233x over previous
#include <cuda_runtime.h>

#define BLOCK 128
#define OPT 4
#define OUTB (BLOCK * OPT)            // 512 outputs per block
#define HALO_L 10
#define HALO_R 6
#define WIN 17                        // positions n-10 .. n+6 for 4 consecutive n
#define TILE (OUTB + HALO_L + HALO_R) // 528 samples; window of last thread ends at OUTB-4+16+? check below

typedef unsigned long long u64;

static __device__ __forceinline__ u64 pk2(float a, float b) {
    u64 v; asm("mov.b64 %0,{%1,%2};" : "=l"(v) : "f"(a), "f"(b)); return v;
}
static __device__ __forceinline__ void up2(u64 v, float& a, float& b) {
    asm("mov.b64 {%0,%1},%2;" : "=f"(a), "=f"(b) : "l"(v));
}
static __device__ __forceinline__ u64 fma2(u64 a, u64 b, u64 c) {
    u64 d; asm("fma.rn.f32x2 %0,%1,%2,%3;" : "=l"(d) : "l"(a), "l"(b), "l"(c)); return d;
}
static __device__ __forceinline__ u64 add2(u64 a, u64 b) {
    u64 d; asm("add.rn.f32x2 %0,%1,%2;" : "=l"(d) : "l"(a), "l"(b)); return d;
}
static __device__ __forceinline__ float fsqrt_ap(float x) {
    float r; asm("sqrt.approx.f32 %0,%1;" : "=f"(r) : "f"(x)); return r;
}

// Merged coefficient table: Q[l][e3][k] packed (re,im) b64; e3 = e+3, e in [-3,3]:
//   e=0  : a[k,l] + b[k,l,0] + c[k,l,0]
//   e=-m : b[k,l,m]   (lagging envelope, position n-l-m)
//   e=+m : c[k,l,m]   (leading envelope, position n-l+m)
__global__ __launch_bounds__(BLOCK)
void gmp_kernel(const float2* __restrict__ x,
                const float* __restrict__ ar, const float* __restrict__ ai,
                const float* __restrict__ br, const float* __restrict__ bi,
                const float* __restrict__ cr, const float* __restrict__ ci,
                float2* __restrict__ y, int N) {
    __shared__ float2 sx[TILE + 4];
    __shared__ __align__(16) u64 sQ[448];

    const int t = threadIdx.x;
    const int base = blockIdx.x * OUTB;

    // Build merged coefficient table (per block; ~10KB global reads, L2-hot)
    for (int i = t; i < 448; i += BLOCK) {
        int k  = i & 7;
        int e3 = (i >> 3) % 7;
        int l  = i / 56;
        int kl = k * 8 + l;                 // a[k][l], row-major (8,8)
        float re, im;
        if (e3 == 3) {
            re = ar[kl] + br[kl * 4] + cr[kl * 4];
            im = ai[kl] + bi[kl * 4] + ci[kl * 4];
        } else if (e3 < 3) {
            int m = 3 - e3;
            re = br[kl * 4 + m]; im = bi[kl * 4 + m];
        } else {
            int m = e3 - 3;
            re = cr[kl * 4 + m]; im = ci[kl * 4 + m];
        }
        sQ[(l * 7 + e3) * 8 + k] = pk2(re, im);
    }
    // Tile load with index clamping (== reference's jnp.clip)
    for (int i = t; i < TILE; i += BLOCK) {
        int g = base - HALO_L + i;
        g = min(max(g, 0), N - 1);
        sx[i] = x[g];
    }
    __syncthreads();

    // Register-cache the 17-sample window for this thread's 4 outputs
    float2 xa[WIN];
    u64 rr[WIN];
    #pragma unroll
    for (int i = 0; i < WIN; i++) {
        float2 v = sx[4 * t + i];          // window start = (base + 4t - 10) -> tile idx 4t
        xa[i] = v;
        float r = fsqrt_ap(fmaf(v.x, v.x, v.y * v.y));
        rr[i] = pk2(r, r);
    }

    float yr[OPT] = {0.f, 0.f, 0.f, 0.f};
    float yi[OPT] = {0.f, 0.f, 0.f, 0.f};

    #pragma unroll
    for (int l = 0; l < 8; l++) {
        u64 w[OPT] = {0ULL, 0ULL, 0ULL, 0ULL};
        #pragma unroll
        for (int e3 = 0; e3 < 7; e3++) {
            const ulonglong2* C = (const ulonglong2*)&sQ[(l * 7 + e3) * 8];
            ulonglong2 c01 = C[0], c23 = C[1], c45 = C[2], c67 = C[3];
            #pragma unroll
            for (int j = 0; j < OPT; j++) {
                u64 r = rr[j - l + e3 + 7];      // compile-time index
                u64 h = fma2(c67.y, r, c67.x);   // c7*r + c6
                h = fma2(h, r, c45.y);
                h = fma2(h, r, c45.x);
                h = fma2(h, r, c23.y);
                h = fma2(h, r, c23.x);
                h = fma2(h, r, c01.y);
                h = fma2(h, r, c01.x);
                w[j] = add2(w[j], h);
            }
        }
        #pragma unroll
        for (int j = 0; j < OPT; j++) {
            float2 xl = xa[j - l + 10];          // carrier x[n-l]
            float wr, wi; up2(w[j], wr, wi);
            yr[j] = fmaf(xl.x, wr, fmaf(-xl.y, wi, yr[j]));
            yi[j] = fmaf(xl.x, wi, fmaf( xl.y, wr, yi[j]));
        }
    }

    int n0 = base + 4 * t;
    if (n0 + 3 < N) {
        float4* y4 = (float4*)y;
        y4[n0 / 2]     = make_float4(yr[0], yi[0], yr[1], yi[1]);
        y4[n0 / 2 + 1] = make_float4(yr[2], yi[2], yr[3], yi[3]);
    } else {
        #pragma unroll
        for (int j = 0; j < OPT; j++)
            if (n0 + j < N) y[n0 + j] = make_float2(yr[j], yi[j]);
    }
}

extern "C" void kernel_launch(void* const* d_in, const int* in_sizes, int n_in,
                              void* d_out, int out_size) {
    const float2* x  = (const float2*)d_in[0];
    const float*  ar = (const float*)d_in[1];
    const float*  ai = (const float*)d_in[2];
    const float*  br = (const float*)d_in[3];
    const float*  bi = (const float*)d_in[4];
    const float*  cr = (const float*)d_in[5];
    const float*  ci = (const float*)d_in[6];
    float2* y = (float2*)d_out;
    int N = in_sizes[0] / 2;

    int grid = (N + OUTB - 1) / OUTB;
    gmp_kernel<<<grid, BLOCK>>>(x, ar, ai, br, bi, cr, ci, y, N);
}